// round 3
// baseline (speedup 1.0000x reference)
#include <cuda_runtime.h>
#include <math.h>
#include <stdint.h>

// Problem constants
#define BB  8
#define LQ  512
#define LK  1024
#define QD  768
#define HID 1024
#define MID 4096
#define NH  16
#define DH  64

// ---------------- scratch (device globals; no allocations allowed) ------------
__device__ float g_qp    [(size_t)BB*LQ*QD];
__device__ float g_qh    [(size_t)BB*LQ*HID];
__device__ float g_q0p   [(size_t)BB*LQ*HID];
__device__ float g_kh    [(size_t)BB*LK*HID];
__device__ float g_v1    [(size_t)BB*LK*HID];
__device__ float g_v0    [(size_t)BB*LK*HID];
__device__ float g_scores[(size_t)BB*NH*LQ*LK];   // 268 MB
__device__ float g_atted [(size_t)BB*LQ*HID];
__device__ float g_tmp   [(size_t)BB*LQ*HID];
__device__ float g_attln [(size_t)BB*LQ*HID];
__device__ float g_h1    [(size_t)BB*LQ*MID];
__device__ float g_ff    [(size_t)BB*LQ*HID];
__device__ float g_xraw  [(size_t)BB*HID];

// ---------------- positional encoding add ------------------------------------
__global__ void add_pe_kernel(const float* __restrict__ in, float* __restrict__ out,
                              int L, size_t total)
{
    size_t idx = (size_t)blockIdx.x * blockDim.x + threadIdx.x;
    if (idx >= total) return;
    int c = (int)(idx % QD);
    int l = (int)((idx / QD) % L);
    const float coef = -9.210340371976184f / 768.0f;   // -ln(10000)/dim
    float ang = (float)l * expf((float)(c & ~1) * coef);
    float pe  = (c & 1) ? cosf(ang) : sinf(ang);
    out[idx] = in[idx] + pe;
}

// ---------------- tiled SGEMM: C = alpha*A@B (+bias, opt relu) ---------------
// A [M,K] row-major lda ; B [K,N] row-major ldb ; C [M,N] ldc.
// Batched via blockIdx.z: z1=z/zdiv, z2=z%zdiv; pointer offsets per (z1,z2).
// All dims assumed multiples of tile sizes (true for this problem).
__global__ void __launch_bounds__(256)
sgemm_nn(const float* __restrict__ A, const float* __restrict__ B,
         const float* __restrict__ bias, float* __restrict__ C,
         int M, int N, int K, int lda, int ldb, int ldc,
         long long offA1, long long offA2,
         long long offB1, long long offB2,
         long long offC1, long long offC2,
         int zdiv, float alpha, int relu)
{
    int z = blockIdx.z;
    int z1 = z / zdiv, z2 = z % zdiv;
    A += (size_t)z1 * offA1 + (size_t)z2 * offA2;
    B += (size_t)z1 * offB1 + (size_t)z2 * offB2;
    C += (size_t)z1 * offC1 + (size_t)z2 * offC2;

    __shared__ __align__(16) float As[16][68];
    __shared__ __align__(16) float Bs[16][68];

    int tid = threadIdx.x;
    int tx = tid & 15, ty = tid >> 4;
    int m0 = blockIdx.y * 64, n0 = blockIdx.x * 64;

    int arow = tid >> 2, acol = (tid & 3) * 4;   // A tile 64x16
    int brow = tid >> 4, bcol = (tid & 15) * 4;  // B tile 16x64

    float acc[4][4] = {};

    for (int k0 = 0; k0 < K; k0 += 16) {
        float4 av = *(const float4*)&A[(size_t)(m0 + arow) * lda + k0 + acol];
        As[acol + 0][arow] = av.x;
        As[acol + 1][arow] = av.y;
        As[acol + 2][arow] = av.z;
        As[acol + 3][arow] = av.w;
        *(float4*)&Bs[brow][bcol] =
            *(const float4*)&B[(size_t)(k0 + brow) * ldb + n0 + bcol];
        __syncthreads();
#pragma unroll
        for (int kk = 0; kk < 16; kk++) {
            float4 a = *(const float4*)&As[kk][ty * 4];
            float4 b = *(const float4*)&Bs[kk][tx * 4];
            float ar[4] = {a.x, a.y, a.z, a.w};
            float br[4] = {b.x, b.y, b.z, b.w};
#pragma unroll
            for (int i = 0; i < 4; i++)
#pragma unroll
                for (int j = 0; j < 4; j++)
                    acc[i][j] += ar[i] * br[j];
        }
        __syncthreads();
    }

#pragma unroll
    for (int i = 0; i < 4; i++) {
        int m = m0 + ty * 4 + i;
#pragma unroll
        for (int j = 0; j < 4; j++) {
            int n = n0 + tx * 4 + j;
            float v = acc[i][j] * alpha;
            if (bias) v += bias[n];
            if (relu) v = fmaxf(v, 0.f);
            C[(size_t)m * ldc + n] = v;
        }
    }
}

// ---------------- tiled SGEMM NT: C[m,n] = alpha * sum_k A[m,k]*B[n,k] -------
__global__ void __launch_bounds__(256)
sgemm_nt(const float* __restrict__ A, const float* __restrict__ B,
         float* __restrict__ C,
         int M, int N, int K, int lda, int ldb, int ldc,
         long long offA1, long long offA2,
         long long offB1, long long offB2,
         long long offC1, long long offC2,
         int zdiv, float alpha)
{
    int z = blockIdx.z;
    int z1 = z / zdiv, z2 = z % zdiv;
    A += (size_t)z1 * offA1 + (size_t)z2 * offA2;
    B += (size_t)z1 * offB1 + (size_t)z2 * offB2;
    C += (size_t)z1 * offC1 + (size_t)z2 * offC2;

    __shared__ __align__(16) float As[16][68];
    __shared__ __align__(16) float Bs[16][68];

    int tid = threadIdx.x;
    int tx = tid & 15, ty = tid >> 4;
    int m0 = blockIdx.y * 64, n0 = blockIdx.x * 64;

    int arow = tid >> 2, acol = (tid & 3) * 4;   // 64 rows x 16 k
    float acc[4][4] = {};

    for (int k0 = 0; k0 < K; k0 += 16) {
        float4 av = *(const float4*)&A[(size_t)(m0 + arow) * lda + k0 + acol];
        As[acol + 0][arow] = av.x;
        As[acol + 1][arow] = av.y;
        As[acol + 2][arow] = av.z;
        As[acol + 3][arow] = av.w;
        float4 bv = *(const float4*)&B[(size_t)(n0 + arow) * ldb + k0 + acol];
        Bs[acol + 0][arow] = bv.x;
        Bs[acol + 1][arow] = bv.y;
        Bs[acol + 2][arow] = bv.z;
        Bs[acol + 3][arow] = bv.w;
        __syncthreads();
#pragma unroll
        for (int kk = 0; kk < 16; kk++) {
            float4 a = *(const float4*)&As[kk][ty * 4];
            float4 b = *(const float4*)&Bs[kk][tx * 4];
            float ar[4] = {a.x, a.y, a.z, a.w};
            float br[4] = {b.x, b.y, b.z, b.w};
#pragma unroll
            for (int i = 0; i < 4; i++)
#pragma unroll
                for (int j = 0; j < 4; j++)
                    acc[i][j] += ar[i] * br[j];
        }
        __syncthreads();
    }

#pragma unroll
    for (int i = 0; i < 4; i++) {
        int m = m0 + ty * 4 + i;
#pragma unroll
        for (int j = 0; j < 4; j++) {
            int n = n0 + tx * 4 + j;
            C[(size_t)m * ldc + n] = acc[i][j] * alpha;
        }
    }
}

// ---------------- att_out = relu(scores).sum(h)/H (pre-softmax) --------------
__global__ void attout_kernel(const float* __restrict__ scores, float* __restrict__ out)
{
    size_t idx = (size_t)blockIdx.x * blockDim.x + threadIdx.x;
    size_t total = (size_t)BB * LQ * LK;
    if (idx >= total) return;
    int k = (int)(idx % LK);
    int q = (int)((idx / LK) % LQ);
    int b = (int)(idx / ((size_t)LK * LQ));
    float s = 0.f;
#pragma unroll
    for (int h = 0; h < NH; h++) {
        float v = scores[(((size_t)(b * NH + h) * LQ) + q) * LK + k];
        s += fmaxf(v, 0.f);
    }
    out[idx] = s * (1.f / (float)NH);
}

// ---------------- in-place softmax over last dim (Lk=1024) -------------------
__global__ void __launch_bounds__(256) softmax_kernel(float* __restrict__ s)
{
    size_t row = blockIdx.x;
    float* p = s + row * (size_t)LK;
    int t = threadIdx.x;
    float v[4];
    float mx = -INFINITY;
#pragma unroll
    for (int i = 0; i < 4; i++) { v[i] = p[t + i * 256]; mx = fmaxf(mx, v[i]); }
    __shared__ float red[256];
    red[t] = mx; __syncthreads();
    for (int o = 128; o > 0; o >>= 1) { if (t < o) red[t] = fmaxf(red[t], red[t + o]); __syncthreads(); }
    mx = red[0]; __syncthreads();
    float sum = 0.f;
#pragma unroll
    for (int i = 0; i < 4; i++) { v[i] = expf(v[i] - mx); sum += v[i]; }
    red[t] = sum; __syncthreads();
    for (int o = 128; o > 0; o >>= 1) { if (t < o) red[t] += red[t + o]; __syncthreads(); }
    float inv = 1.f / red[0];
#pragma unroll
    for (int i = 0; i < 4; i++) p[t + i * 256] = v[i] * inv;
}

// ---------------- bilinear reduce: x_raw[b,c] = sum_q q0p[b,q,c]*tmp[b,q,c] --
__global__ void bilinear_kernel(const float* __restrict__ q0p,
                                const float* __restrict__ tmp,
                                float* __restrict__ xraw)
{
    int c = blockIdx.x * blockDim.x + threadIdx.x;  // 0..1023
    int b = blockIdx.y;
    const float* a = q0p + (size_t)b * LQ * HID + c;
    const float* t = tmp + (size_t)b * LQ * HID + c;
    float s = 0.f;
    for (int v = 0; v < LQ; v++)
        s += a[(size_t)v * HID] * t[(size_t)v * HID];
    xraw[b * HID + c] = s;
}

// ---------------- custom LayerNorm: a*(x-mean)/(std_unbiased+eps)+b ----------
// optional second addend (residual). n = HID = 1024.
__global__ void __launch_bounds__(256)
ln_kernel(const float* __restrict__ in1, const float* __restrict__ in2,
          const float* __restrict__ ga, const float* __restrict__ gb,
          float* __restrict__ out)
{
    size_t row = blockIdx.x;
    int t = threadIdx.x;
    const float* p1 = in1 + row * (size_t)HID;
    const float* p2 = in2 ? in2 + row * (size_t)HID : nullptr;
    float v[4];
    float s = 0.f;
#pragma unroll
    for (int i = 0; i < 4; i++) {
        int c = t + i * 256;
        v[i] = p1[c] + (p2 ? p2[c] : 0.f);
        s += v[i];
    }
    __shared__ float red[256];
    red[t] = s; __syncthreads();
    for (int o = 128; o > 0; o >>= 1) { if (t < o) red[t] += red[t + o]; __syncthreads(); }
    float mean = red[0] * (1.f / (float)HID);
    __syncthreads();
    float s2 = 0.f;
#pragma unroll
    for (int i = 0; i < 4; i++) { float d = v[i] - mean; s2 += d * d; }
    red[t] = s2; __syncthreads();
    for (int o = 128; o > 0; o >>= 1) { if (t < o) red[t] += red[t + o]; __syncthreads(); }
    float var = red[0] * (1.f / (float)(HID - 1));   // unbiased, torch default
    float inv = 1.f / (sqrtf(var) + 1e-6f);          // eps added to STD
#pragma unroll
    for (int i = 0; i < 4; i++) {
        int c = t + i * 256;
        out[row * (size_t)HID + c] = ga[c] * (v[i] - mean) * inv + gb[c];
    }
}

// =============================================================================
extern "C" void kernel_launch(void* const* d_in, const int* in_sizes, int n_in,
                              void* d_out, int out_size)
{
    const float* q    = (const float*)d_in[0];
    const float* k    = (const float*)d_in[1];
    const float* Wq   = (const float*)d_in[2];
    const float* bq   = (const float*)d_in[3];
    const float* Wk   = (const float*)d_in[4];
    const float* bk   = (const float*)d_in[5];
    const float* Wv   = (const float*)d_in[6];
    const float* bv   = (const float*)d_in[7];
    const float* Wv0  = (const float*)d_in[8];
    const float* bv0  = (const float*)d_in[9];
    const float* Wq0  = (const float*)d_in[10];
    const float* bq0  = (const float*)d_in[11];
    const float* nq_a = (const float*)d_in[12];
    const float* nq_b = (const float*)d_in[13];
    const float* nx_a = (const float*)d_in[14];
    const float* nx_b = (const float*)d_in[15];
    const float* W1   = (const float*)d_in[16];
    const float* b1   = (const float*)d_in[17];
    const float* W2   = (const float*)d_in[18];
    const float* b2   = (const float*)d_in[19];
    const float* ns_a = (const float*)d_in[20];
    const float* ns_b = (const float*)d_in[21];

    float* out = (float*)d_out;
    // output layout: x | qq | kp | att_out
    const size_t OFF_X   = 0;
    const size_t OFF_QQ  = OFF_X  + (size_t)BB * HID;
    const size_t OFF_KP  = OFF_QQ + (size_t)BB * LQ * HID;
    const size_t OFF_ATT = OFF_KP + (size_t)BB * LK * QD;

    float *qp, *qh, *q0p, *kh, *v1, *v0, *scores, *atted, *tmp, *attln, *h1, *ff, *xraw;
    cudaGetSymbolAddress((void**)&qp,     g_qp);
    cudaGetSymbolAddress((void**)&qh,     g_qh);
    cudaGetSymbolAddress((void**)&q0p,    g_q0p);
    cudaGetSymbolAddress((void**)&kh,     g_kh);
    cudaGetSymbolAddress((void**)&v1,     g_v1);
    cudaGetSymbolAddress((void**)&v0,     g_v0);
    cudaGetSymbolAddress((void**)&scores, g_scores);
    cudaGetSymbolAddress((void**)&atted,  g_atted);
    cudaGetSymbolAddress((void**)&tmp,    g_tmp);
    cudaGetSymbolAddress((void**)&attln,  g_attln);
    cudaGetSymbolAddress((void**)&h1,     g_h1);
    cudaGetSymbolAddress((void**)&ff,     g_ff);
    cudaGetSymbolAddress((void**)&xraw,   g_xraw);

    float* kp = out + OFF_KP;   // kp is an output AND an intermediate

    // 1) positional encodings
    {
        size_t tq = (size_t)BB * LQ * QD;
        add_pe_kernel<<<(unsigned)((tq + 255) / 256), 256>>>(q, qp, LQ, tq);
        size_t tk = (size_t)BB * LK * QD;
        add_pe_kernel<<<(unsigned)((tk + 255) / 256), 256>>>(k, kp, LK, tk);
    }

    const int MQ = BB * LQ;     // 4096
    const int MK = BB * LK;     // 8192

    // 2) projections
    sgemm_nn<<<dim3(HID / 64, MQ / 64, 1), 256>>>(qp, Wq, bq, qh,
        MQ, HID, QD, QD, HID, HID, 0, 0, 0, 0, 0, 0, 1, 1.f, 0);
    sgemm_nn<<<dim3(HID / 64, MQ / 64, 1), 256>>>(q, Wq0, bq0, q0p,
        MQ, HID, QD, QD, HID, HID, 0, 0, 0, 0, 0, 0, 1, 1.f, 0);
    sgemm_nn<<<dim3(HID / 64, MK / 64, 1), 256>>>(kp, Wk, bk, kh,
        MK, HID, QD, QD, HID, HID, 0, 0, 0, 0, 0, 0, 1, 1.f, 0);
    sgemm_nn<<<dim3(HID / 64, MK / 64, 1), 256>>>(kp, Wv, bv, v1,
        MK, HID, QD, QD, HID, HID, 0, 0, 0, 0, 0, 0, 1, 1.f, 0);
    sgemm_nn<<<dim3(HID / 64, MK / 64, 1), 256>>>(kp, Wv0, bv0, v0,
        MK, HID, QD, QD, HID, HID, 0, 0, 0, 0, 0, 0, 1, 1.f, 0);

    // 3) scores[b,h] = qh_h @ kh_h^T / sqrt(dh)   (batched z = b*16+h)
    sgemm_nt<<<dim3(LK / 64, LQ / 64, BB * NH), 256>>>(qh, kh, scores,
        LQ, LK, DH, HID, HID, LK,
        /*A*/ (long long)LQ * HID, (long long)DH,
        /*B*/ (long long)LK * HID, (long long)DH,
        /*C*/ (long long)NH * LQ * LK, (long long)LQ * LK,
        NH, 0.125f);

    // 4) att_out (pre-softmax)
    {
        size_t tot = (size_t)BB * LQ * LK;
        attout_kernel<<<(unsigned)((tot + 255) / 256), 256>>>(scores, out + OFF_ATT);
    }

    // 5) softmax in place -> att
    softmax_kernel<<<BB * NH * LQ, 256>>>(scores);

    // 6) atted_raw = att @ v1 ; tmp = att @ v0   (batched M=512,N=64,K=1024)
    sgemm_nn<<<dim3(1, LQ / 64, BB * NH), 256>>>(scores, v1, nullptr, atted,
        LQ, DH, LK, LK, HID, HID,
        /*A*/ (long long)NH * LQ * LK, (long long)LQ * LK,
        /*B*/ (long long)LK * HID, (long long)DH,
        /*C*/ (long long)LQ * HID, (long long)DH,
        NH, 1.f, 0);
    sgemm_nn<<<dim3(1, LQ / 64, BB * NH), 256>>>(scores, v0, nullptr, tmp,
        LQ, DH, LK, LK, HID, HID,
        (long long)NH * LQ * LK, (long long)LQ * LK,
        (long long)LK * HID, (long long)DH,
        (long long)LQ * HID, (long long)DH,
        NH, 1.f, 0);

    // 7) bilinear reduce + LN -> x
    bilinear_kernel<<<dim3(HID / 256, BB), 256>>>(q0p, tmp, xraw);
    ln_kernel<<<BB, 256>>>(xraw, nullptr, nx_a, nx_b, out + OFF_X);

    // 8) atted = LN(q0p + atted_raw)
    ln_kernel<<<MQ, 256>>>(q0p, atted, nq_a, nq_b, attln);

    // 9) FFN + residual LN -> qq
    sgemm_nn<<<dim3(MID / 64, MQ / 64, 1), 256>>>(attln, W1, b1, h1,
        MQ, MID, HID, HID, MID, MID, 0, 0, 0, 0, 0, 0, 1, 1.f, 1);
    sgemm_nn<<<dim3(HID / 64, MQ / 64, 1), 256>>>(h1, W2, b2, ff,
        MQ, HID, MID, MID, HID, HID, 0, 0, 0, 0, 0, 0, 1, 1.f, 0);
    ln_kernel<<<MQ, 256>>>(attln, ff, ns_a, ns_b, out + OFF_QQ);
}

// round 5
// speedup vs baseline: 1.9416x; 1.9416x over previous
#include <cuda_runtime.h>
#include <cuda_bf16.h>
#include <math.h>
#include <stdint.h>

// Problem constants
#define BB  8
#define LQ  512
#define LK  1024
#define QD  768
#define HID 1024
#define MID 4096
#define NH  16
#define DH  64

// ---------------- scratch (device globals; no allocations allowed) ------------
__device__ float g_qp    [(size_t)BB*LQ*QD];
__device__ float g_qh    [(size_t)BB*LQ*HID];
__device__ float g_q0p   [(size_t)BB*LQ*HID];
__device__ float g_kh    [(size_t)BB*LK*HID];
__device__ float g_v1    [(size_t)BB*LK*HID];
__device__ float g_v0    [(size_t)BB*LK*HID];
__device__ float g_scores[(size_t)BB*NH*LQ*LK];   // 268 MB
__device__ float g_atted [(size_t)BB*LQ*HID];
__device__ float g_tmp   [(size_t)BB*LQ*HID];
__device__ float g_attln [(size_t)BB*LQ*HID];
__device__ float g_ff    [(size_t)BB*LQ*HID];
__device__ float g_xraw  [(size_t)BB*HID];

// bf16 split operands (A' = [hi|lo|hi], B' = [hi|hi|lo] along K)
__device__ __nv_bfloat16 g_qpbf   [(size_t)BB*LQ*3*QD];
__device__ __nv_bfloat16 g_qbf    [(size_t)BB*LQ*3*QD];
__device__ __nv_bfloat16 g_kpbf   [(size_t)BB*LK*3*QD];
__device__ __nv_bfloat16 g_attlnbf[(size_t)BB*LQ*3*HID];
__device__ __nv_bfloat16 g_h1bf   [(size_t)BB*LQ*3*MID];   // from FFN1 epilogue
__device__ __nv_bfloat16 g_Wqbf  [(size_t)HID*3*QD];
__device__ __nv_bfloat16 g_Wq0bf [(size_t)HID*3*QD];
__device__ __nv_bfloat16 g_Wkbf  [(size_t)HID*3*QD];
__device__ __nv_bfloat16 g_Wvbf  [(size_t)HID*3*QD];
__device__ __nv_bfloat16 g_Wv0bf [(size_t)HID*3*QD];
__device__ __nv_bfloat16 g_W1bf  [(size_t)MID*3*HID];
__device__ __nv_bfloat16 g_W2bf  [(size_t)HID*3*MID];

// =================== helpers ==================================================
__device__ __forceinline__ uint32_t smem_u32(const void* p) {
    uint32_t a;
    asm("{ .reg .u64 t; cvta.to.shared.u64 t, %1; cvt.u32.u64 %0, t; }"
        : "=r"(a) : "l"(p));
    return a;
}
#define SWZ128(x) ((x) ^ (((x) >> 3) & 0x70))

__device__ __forceinline__ void cp_async16(uint32_t dst, const void* src) {
    asm volatile("cp.async.cg.shared.global [%0], [%1], 16;"
                 :: "r"(dst), "l"(src) : "memory");
}
#define CP_COMMIT() asm volatile("cp.async.commit_group;" ::: "memory")
#define CP_WAIT(n)  asm volatile("cp.async.wait_group %0;" :: "n"(n) : "memory")

__device__ __forceinline__ void ldsm_x4(uint32_t& r0, uint32_t& r1,
                                        uint32_t& r2, uint32_t& r3, uint32_t a) {
    asm volatile("ldmatrix.sync.aligned.m8n8.x4.shared.b16 {%0,%1,%2,%3}, [%4];"
                 : "=r"(r0), "=r"(r1), "=r"(r2), "=r"(r3) : "r"(a));
}
__device__ __forceinline__ void mma16816(float* c, const uint32_t* a,
                                         uint32_t b0, uint32_t b1) {
    asm volatile("mma.sync.aligned.m16n8k16.row.col.f32.bf16.bf16.f32 "
                 "{%0,%1,%2,%3}, {%4,%5,%6,%7}, {%8,%9}, {%0,%1,%2,%3};"
                 : "+f"(c[0]), "+f"(c[1]), "+f"(c[2]), "+f"(c[3])
                 : "r"(a[0]), "r"(a[1]), "r"(a[2]), "r"(a[3]), "r"(b0), "r"(b1));
}

// ---------------- split conversions ------------------------------------------
// A' row m: [hi(0..K-1) | lo | hi]
__global__ void convA_split(const float* __restrict__ in, __nv_bfloat16* __restrict__ out,
                            int K, size_t total)
{
    size_t idx = (size_t)blockIdx.x * blockDim.x + threadIdx.x;
    if (idx >= total) return;
    size_t m = idx / K;
    int    k = (int)(idx % K);
    float x = in[idx];
    __nv_bfloat16 hi = __float2bfloat16(x);
    __nv_bfloat16 lo = __float2bfloat16(x - __bfloat162float(hi));
    __nv_bfloat16* row = out + m * (size_t)(3 * K);
    row[k] = hi; row[K + k] = lo; row[2 * K + k] = hi;
}

// B [K,N] fp32 -> B' [N, 3K] bf16 (transposed): [hi | hi | lo]
__global__ void convB_split(const float* __restrict__ W, __nv_bfloat16* __restrict__ out,
                            int K, int N)
{
    __shared__ float t[32][33];
    int k0 = blockIdx.x * 32, n0 = blockIdx.y * 32;
    int x = threadIdx.x, y = threadIdx.y;   // 32 x 8
#pragma unroll
    for (int i = 0; i < 32; i += 8)
        t[y + i][x] = W[(size_t)(k0 + y + i) * N + n0 + x];
    __syncthreads();
    int K3 = 3 * K;
#pragma unroll
    for (int i = 0; i < 32; i += 8) {
        int n = n0 + y + i, k = k0 + x;
        float v = t[x][y + i];
        __nv_bfloat16 hi = __float2bfloat16(v);
        __nv_bfloat16 lo = __float2bfloat16(v - __bfloat162float(hi));
        __nv_bfloat16* row = out + (size_t)n * K3;
        row[k] = hi; row[K + k] = hi; row[2 * K + k] = lo;
    }
}

// ---------------- bf16 mma.sync GEMM: C[M,N] = A'[M,K3] x B'[N,K3]^T ---------
// 128x128 CTA tile, 8 warps (4x2), warp tile 32m x 64n, BK=64 bf16, 2-stage
// cp.async pipeline, SW128 swizzle, ldmatrix operand loads.
// Optional split-bf16 output Osp ([hi|lo|hi] along N-segment Kseg) for FFN1.
#define GEMM_SMEM_BYTES (2 * (16384 + 16384))

__global__ void __launch_bounds__(256, 2)
gemm_mma(const __nv_bfloat16* __restrict__ A, const __nv_bfloat16* __restrict__ B,
         const float* __restrict__ bias, float* __restrict__ C,
         __nv_bfloat16* __restrict__ Osp,
         int K3, int ldc, int Kseg, int relu)
{
    extern __shared__ uint8_t dynsmem[];
    const uint32_t sb = smem_u32(dynsmem);
    const int tid = threadIdx.x;
    const int wid = tid >> 5, lane = tid & 31;
    const int m0 = blockIdx.y * 128, n0 = blockIdx.x * 128;
    const int wm = (wid & 3) * 32, wn = (wid >> 2) * 64;

    const size_t abase = (size_t)m0 * K3;
    const size_t bbase = (size_t)n0 * K3;
    const int nch = K3 >> 6;

    float acc[2][8][4] = {};

    // ---- async load of one 64-k chunk into stage st ----
    auto load_stage = [&](int st, int ch) {
        size_t koff = (size_t)ch * 64;
        uint32_t base = (uint32_t)st * 32768u;
#pragma unroll
        for (int i = 0; i < 4; i++) {
            int idx = tid + i * 256;
            int r = idx >> 3, c = idx & 7;
            uint32_t so = SWZ128((uint32_t)(r * 128 + c * 16));
            cp_async16(sb + base + so, A + abase + (size_t)r * K3 + koff + c * 8);
            cp_async16(sb + base + 16384u + so, B + bbase + (size_t)r * K3 + koff + c * 8);
        }
        CP_COMMIT();
    };

    load_stage(0, 0);

    for (int ch = 0; ch < nch; ch++) {
        if (ch + 1 < nch) { load_stage((ch + 1) & 1, ch + 1); CP_WAIT(1); }
        else              { CP_WAIT(0); }
        __syncthreads();

        uint32_t As = sb + (uint32_t)(ch & 1) * 32768u;
        uint32_t Bs = As + 16384u;
#pragma unroll
        for (int ks = 0; ks < 4; ks++) {
            int kb = ks * 32 + ((lane >> 4) << 4);
            uint32_t a[2][4];
#pragma unroll
            for (int mi = 0; mi < 2; mi++) {
                int r = wm + mi * 16 + (lane & 15);
                ldsm_x4(a[mi][0], a[mi][1], a[mi][2], a[mi][3],
                        As + SWZ128((uint32_t)(r * 128 + kb)));
            }
            uint32_t b[4][4];
#pragma unroll
            for (int g = 0; g < 4; g++) {
                int r = wn + g * 16 + (lane & 15);
                ldsm_x4(b[g][0], b[g][1], b[g][2], b[g][3],
                        Bs + SWZ128((uint32_t)(r * 128 + kb)));
            }
#pragma unroll
            for (int mi = 0; mi < 2; mi++)
#pragma unroll
                for (int nj = 0; nj < 8; nj++) {
                    int g = nj >> 1;
                    uint32_t b0 = (nj & 1) ? b[g][1] : b[g][0];
                    uint32_t b1 = (nj & 1) ? b[g][3] : b[g][2];
                    mma16816(acc[mi][nj], a[mi], b0, b1);
                }
        }
        __syncthreads();
    }

    // ---- epilogue ----
    int rowg = lane >> 2, colg = (lane & 3) * 2;
#pragma unroll
    for (int mi = 0; mi < 2; mi++) {
#pragma unroll
        for (int nj = 0; nj < 8; nj++) {
            int r0 = m0 + wm + mi * 16 + rowg;
            int c0 = n0 + wn + nj * 8 + colg;
            float v0 = acc[mi][nj][0], v1 = acc[mi][nj][1];
            float v2 = acc[mi][nj][2], v3 = acc[mi][nj][3];
            if (bias) {
                float b0 = bias[c0], b1 = bias[c0 + 1];
                v0 += b0; v1 += b1; v2 += b0; v3 += b1;
            }
            if (relu) {
                v0 = fmaxf(v0, 0.f); v1 = fmaxf(v1, 0.f);
                v2 = fmaxf(v2, 0.f); v3 = fmaxf(v3, 0.f);
            }
            if (C) {
                float2 p0 = {v0, v1}, p1 = {v2, v3};
                *(float2*)(C + (size_t)r0 * ldc + c0)       = p0;
                *(float2*)(C + (size_t)(r0 + 8) * ldc + c0) = p1;
            }
            if (Osp) {
                size_t K3o = (size_t)(3 * Kseg);
                __nv_bfloat16 h0 = __float2bfloat16(v0);
                __nv_bfloat16 h1 = __float2bfloat16(v1);
                __nv_bfloat162 hp; hp.x = h0; hp.y = h1;
                __nv_bfloat162 lp;
                lp.x = __float2bfloat16(v0 - __bfloat162float(h0));
                lp.y = __float2bfloat16(v1 - __bfloat162float(h1));
                __nv_bfloat16* rw = Osp + (size_t)r0 * K3o + c0;
                *(__nv_bfloat162*)(rw)            = hp;
                *(__nv_bfloat162*)(rw + Kseg)     = lp;
                *(__nv_bfloat162*)(rw + 2 * Kseg) = hp;
                h0 = __float2bfloat16(v2);
                h1 = __float2bfloat16(v3);
                hp.x = h0; hp.y = h1;
                lp.x = __float2bfloat16(v2 - __bfloat162float(h0));
                lp.y = __float2bfloat16(v3 - __bfloat162float(h1));
                rw = Osp + (size_t)(r0 + 8) * K3o + c0;
                *(__nv_bfloat162*)(rw)            = hp;
                *(__nv_bfloat162*)(rw + Kseg)     = lp;
                *(__nv_bfloat162*)(rw + 2 * Kseg) = hp;
            }
        }
    }
}

// ---------------- positional encoding add ------------------------------------
__global__ void add_pe_kernel(const float* __restrict__ in, float* __restrict__ out,
                              int L, size_t total)
{
    size_t idx = (size_t)blockIdx.x * blockDim.x + threadIdx.x;
    if (idx >= total) return;
    int c = (int)(idx % QD);
    int l = (int)((idx / QD) % L);
    const float coef = -9.210340371976184f / 768.0f;   // -ln(10000)/dim
    float ang = (float)l * expf((float)(c & ~1) * coef);
    float pe  = (c & 1) ? cosf(ang) : sinf(ang);
    out[idx] = in[idx] + pe;
}

// ---------------- fp32 tiled SGEMM (att@V) -----------------------------------
__global__ void __launch_bounds__(256)
sgemm_nn(const float* __restrict__ A, const float* __restrict__ B,
         const float* __restrict__ bias, float* __restrict__ C,
         int M, int N, int K, int lda, int ldb, int ldc,
         long long offA1, long long offA2,
         long long offB1, long long offB2,
         long long offC1, long long offC2,
         int zdiv, float alpha, int relu)
{
    int z = blockIdx.z;
    int z1 = z / zdiv, z2 = z % zdiv;
    A += (size_t)z1 * offA1 + (size_t)z2 * offA2;
    B += (size_t)z1 * offB1 + (size_t)z2 * offB2;
    C += (size_t)z1 * offC1 + (size_t)z2 * offC2;

    __shared__ __align__(16) float As[16][68];
    __shared__ __align__(16) float Bs[16][68];

    int tid = threadIdx.x;
    int tx = tid & 15, ty = tid >> 4;
    int m0 = blockIdx.y * 64, n0 = blockIdx.x * 64;

    int arow = tid >> 2, acol = (tid & 3) * 4;
    int brow = tid >> 4, bcol = (tid & 15) * 4;

    float acc[4][4] = {};

    for (int k0 = 0; k0 < K; k0 += 16) {
        float4 av = *(const float4*)&A[(size_t)(m0 + arow) * lda + k0 + acol];
        As[acol + 0][arow] = av.x;
        As[acol + 1][arow] = av.y;
        As[acol + 2][arow] = av.z;
        As[acol + 3][arow] = av.w;
        *(float4*)&Bs[brow][bcol] =
            *(const float4*)&B[(size_t)(k0 + brow) * ldb + n0 + bcol];
        __syncthreads();
#pragma unroll
        for (int kk = 0; kk < 16; kk++) {
            float4 a = *(const float4*)&As[kk][ty * 4];
            float4 b = *(const float4*)&Bs[kk][tx * 4];
            float ar[4] = {a.x, a.y, a.z, a.w};
            float br[4] = {b.x, b.y, b.z, b.w};
#pragma unroll
            for (int i = 0; i < 4; i++)
#pragma unroll
                for (int j = 0; j < 4; j++)
                    acc[i][j] += ar[i] * br[j];
        }
        __syncthreads();
    }

#pragma unroll
    for (int i = 0; i < 4; i++) {
        int m = m0 + ty * 4 + i;
#pragma unroll
        for (int j = 0; j < 4; j++) {
            int n = n0 + tx * 4 + j;
            float v = acc[i][j] * alpha;
            if (bias) v += bias[n];
            if (relu) v = fmaxf(v, 0.f);
            C[(size_t)m * ldc + n] = v;
        }
    }
}

// ---------------- fp32 SGEMM NT (scores) -------------------------------------
__global__ void __launch_bounds__(256)
sgemm_nt(const float* __restrict__ A, const float* __restrict__ B,
         float* __restrict__ C,
         int M, int N, int K, int lda, int ldb, int ldc,
         long long offA1, long long offA2,
         long long offB1, long long offB2,
         long long offC1, long long offC2,
         int zdiv, float alpha)
{
    int z = blockIdx.z;
    int z1 = z / zdiv, z2 = z % zdiv;
    A += (size_t)z1 * offA1 + (size_t)z2 * offA2;
    B += (size_t)z1 * offB1 + (size_t)z2 * offB2;
    C += (size_t)z1 * offC1 + (size_t)z2 * offC2;

    __shared__ __align__(16) float As[16][68];
    __shared__ __align__(16) float Bs[16][68];

    int tid = threadIdx.x;
    int tx = tid & 15, ty = tid >> 4;
    int m0 = blockIdx.y * 64, n0 = blockIdx.x * 64;

    int arow = tid >> 2, acol = (tid & 3) * 4;
    float acc[4][4] = {};

    for (int k0 = 0; k0 < K; k0 += 16) {
        float4 av = *(const float4*)&A[(size_t)(m0 + arow) * lda + k0 + acol];
        As[acol + 0][arow] = av.x;
        As[acol + 1][arow] = av.y;
        As[acol + 2][arow] = av.z;
        As[acol + 3][arow] = av.w;
        float4 bv = *(const float4*)&B[(size_t)(n0 + arow) * ldb + k0 + acol];
        Bs[acol + 0][arow] = bv.x;
        Bs[acol + 1][arow] = bv.y;
        Bs[acol + 2][arow] = bv.z;
        Bs[acol + 3][arow] = bv.w;
        __syncthreads();
#pragma unroll
        for (int kk = 0; kk < 16; kk++) {
            float4 a = *(const float4*)&As[kk][ty * 4];
            float4 b = *(const float4*)&Bs[kk][tx * 4];
            float ar[4] = {a.x, a.y, a.z, a.w};
            float br[4] = {b.x, b.y, b.z, b.w};
#pragma unroll
            for (int i = 0; i < 4; i++)
#pragma unroll
                for (int j = 0; j < 4; j++)
                    acc[i][j] += ar[i] * br[j];
        }
        __syncthreads();
    }

#pragma unroll
    for (int i = 0; i < 4; i++) {
        int m = m0 + ty * 4 + i;
#pragma unroll
        for (int j = 0; j < 4; j++) {
            int n = n0 + tx * 4 + j;
            C[(size_t)m * ldc + n] = acc[i][j] * alpha;
        }
    }
}

// ---------------- att_out = relu(scores).sum(h)/H (pre-softmax) --------------
__global__ void attout_kernel(const float* __restrict__ scores, float* __restrict__ out)
{
    size_t idx = (size_t)blockIdx.x * blockDim.x + threadIdx.x;
    size_t total = (size_t)BB * LQ * LK;
    if (idx >= total) return;
    int k = (int)(idx % LK);
    int q = (int)((idx / LK) % LQ);
    int b = (int)(idx / ((size_t)LK * LQ));
    float s = 0.f;
#pragma unroll
    for (int h = 0; h < NH; h++) {
        float v = scores[(((size_t)(b * NH + h) * LQ) + q) * LK + k];
        s += fmaxf(v, 0.f);
    }
    out[idx] = s * (1.f / (float)NH);
}

// ---------------- in-place softmax over last dim (Lk=1024) -------------------
__global__ void __launch_bounds__(256) softmax_kernel(float* __restrict__ s)
{
    size_t row = blockIdx.x;
    float* p = s + row * (size_t)LK;
    int t = threadIdx.x;
    float v[4];
    float mx = -INFINITY;
#pragma unroll
    for (int i = 0; i < 4; i++) { v[i] = p[t + i * 256]; mx = fmaxf(mx, v[i]); }
    __shared__ float red[256];
    red[t] = mx; __syncthreads();
    for (int o = 128; o > 0; o >>= 1) { if (t < o) red[t] = fmaxf(red[t], red[t + o]); __syncthreads(); }
    mx = red[0]; __syncthreads();
    float sum = 0.f;
#pragma unroll
    for (int i = 0; i < 4; i++) { v[i] = expf(v[i] - mx); sum += v[i]; }
    red[t] = sum; __syncthreads();
    for (int o = 128; o > 0; o >>= 1) { if (t < o) red[t] += red[t + o]; __syncthreads(); }
    float inv = 1.f / red[0];
#pragma unroll
    for (int i = 0; i < 4; i++) p[t + i * 256] = v[i] * inv;
}

// ---------------- bilinear reduce --------------------------------------------
__global__ void bilinear_kernel(const float* __restrict__ q0p,
                                const float* __restrict__ tmp,
                                float* __restrict__ xraw)
{
    int c = blockIdx.x * blockDim.x + threadIdx.x;
    int b = blockIdx.y;
    const float* a = q0p + (size_t)b * LQ * HID + c;
    const float* t = tmp + (size_t)b * LQ * HID + c;
    float s = 0.f;
    for (int v = 0; v < LQ; v++)
        s += a[(size_t)v * HID] * t[(size_t)v * HID];
    xraw[b * HID + c] = s;
}

// ---------------- custom LayerNorm -------------------------------------------
__global__ void __launch_bounds__(256)
ln_kernel(const float* __restrict__ in1, const float* __restrict__ in2,
          const float* __restrict__ ga, const float* __restrict__ gb,
          float* __restrict__ out)
{
    size_t row = blockIdx.x;
    int t = threadIdx.x;
    const float* p1 = in1 + row * (size_t)HID;
    const float* p2 = in2 ? in2 + row * (size_t)HID : nullptr;
    float v[4];
    float s = 0.f;
#pragma unroll
    for (int i = 0; i < 4; i++) {
        int c = t + i * 256;
        v[i] = p1[c] + (p2 ? p2[c] : 0.f);
        s += v[i];
    }
    __shared__ float red[256];
    red[t] = s; __syncthreads();
    for (int o = 128; o > 0; o >>= 1) { if (t < o) red[t] += red[t + o]; __syncthreads(); }
    float mean = red[0] * (1.f / (float)HID);
    __syncthreads();
    float s2 = 0.f;
#pragma unroll
    for (int i = 0; i < 4; i++) { float d = v[i] - mean; s2 += d * d; }
    red[t] = s2; __syncthreads();
    for (int o = 128; o > 0; o >>= 1) { if (t < o) red[t] += red[t + o]; __syncthreads(); }
    float var = red[0] * (1.f / (float)(HID - 1));
    float inv = 1.f / (sqrtf(var) + 1e-6f);
#pragma unroll
    for (int i = 0; i < 4; i++) {
        int c = t + i * 256;
        out[row * (size_t)HID + c] = ga[c] * (v[i] - mean) * inv + gb[c];
    }
}

// =============================================================================
extern "C" void kernel_launch(void* const* d_in, const int* in_sizes, int n_in,
                              void* d_out, int out_size)
{
    const float* q    = (const float*)d_in[0];
    const float* k    = (const float*)d_in[1];
    const float* Wq   = (const float*)d_in[2];
    const float* bq   = (const float*)d_in[3];
    const float* Wk   = (const float*)d_in[4];
    const float* bk   = (const float*)d_in[5];
    const float* Wv   = (const float*)d_in[6];
    const float* bv   = (const float*)d_in[7];
    const float* Wv0  = (const float*)d_in[8];
    const float* bv0  = (const float*)d_in[9];
    const float* Wq0  = (const float*)d_in[10];
    const float* bq0  = (const float*)d_in[11];
    const float* nq_a = (const float*)d_in[12];
    const float* nq_b = (const float*)d_in[13];
    const float* nx_a = (const float*)d_in[14];
    const float* nx_b = (const float*)d_in[15];
    const float* W1   = (const float*)d_in[16];
    const float* b1   = (const float*)d_in[17];
    const float* W2   = (const float*)d_in[18];
    const float* b2   = (const float*)d_in[19];
    const float* ns_a = (const float*)d_in[20];
    const float* ns_b = (const float*)d_in[21];

    float* out = (float*)d_out;
    const size_t OFF_X   = 0;
    const size_t OFF_QQ  = OFF_X  + (size_t)BB * HID;
    const size_t OFF_KP  = OFF_QQ + (size_t)BB * LQ * HID;
    const size_t OFF_ATT = OFF_KP + (size_t)BB * LK * QD;

    float *qp, *qh, *q0p, *kh, *v1, *v0, *scores, *atted, *tmp, *attln, *ff, *xraw;
    __nv_bfloat16 *qpbf, *qbf, *kpbf, *attlnbf, *h1bf;
    __nv_bfloat16 *Wqbf, *Wq0bf, *Wkbf, *Wvbf, *Wv0bf, *W1bf, *W2bf;
    cudaGetSymbolAddress((void**)&qp,     g_qp);
    cudaGetSymbolAddress((void**)&qh,     g_qh);
    cudaGetSymbolAddress((void**)&q0p,    g_q0p);
    cudaGetSymbolAddress((void**)&kh,     g_kh);
    cudaGetSymbolAddress((void**)&v1,     g_v1);
    cudaGetSymbolAddress((void**)&v0,     g_v0);
    cudaGetSymbolAddress((void**)&scores, g_scores);
    cudaGetSymbolAddress((void**)&atted,  g_atted);
    cudaGetSymbolAddress((void**)&tmp,    g_tmp);
    cudaGetSymbolAddress((void**)&attln,  g_attln);
    cudaGetSymbolAddress((void**)&ff,     g_ff);
    cudaGetSymbolAddress((void**)&xraw,   g_xraw);
    cudaGetSymbolAddress((void**)&qpbf,   g_qpbf);
    cudaGetSymbolAddress((void**)&qbf,    g_qbf);
    cudaGetSymbolAddress((void**)&kpbf,   g_kpbf);
    cudaGetSymbolAddress((void**)&attlnbf,g_attlnbf);
    cudaGetSymbolAddress((void**)&h1bf,   g_h1bf);
    cudaGetSymbolAddress((void**)&Wqbf,   g_Wqbf);
    cudaGetSymbolAddress((void**)&Wq0bf,  g_Wq0bf);
    cudaGetSymbolAddress((void**)&Wkbf,   g_Wkbf);
    cudaGetSymbolAddress((void**)&Wvbf,   g_Wvbf);
    cudaGetSymbolAddress((void**)&Wv0bf,  g_Wv0bf);
    cudaGetSymbolAddress((void**)&W1bf,   g_W1bf);
    cudaGetSymbolAddress((void**)&W2bf,   g_W2bf);

    cudaFuncSetAttribute(gemm_mma, cudaFuncAttributeMaxDynamicSharedMemorySize,
                         GEMM_SMEM_BYTES);

    float* kp = out + OFF_KP;

    // 1) positional encodings
    {
        size_t tq = (size_t)BB * LQ * QD;
        add_pe_kernel<<<(unsigned)((tq + 255) / 256), 256>>>(q, qp, LQ, tq);
        size_t tk = (size_t)BB * LK * QD;
        add_pe_kernel<<<(unsigned)((tk + 255) / 256), 256>>>(k, kp, LK, tk);
    }

    const int MQ = BB * LQ;     // 4096
    const int MK = BB * LK;     // 8192

    // 2) split conversions
    {
        size_t t1 = (size_t)MQ * QD;
        convA_split<<<(unsigned)((t1 + 255) / 256), 256>>>(qp, qpbf, QD, t1);
        convA_split<<<(unsigned)((t1 + 255) / 256), 256>>>(q,  qbf,  QD, t1);
        size_t t2 = (size_t)MK * QD;
        convA_split<<<(unsigned)((t2 + 255) / 256), 256>>>(kp, kpbf, QD, t2);
        dim3 bb(32, 8);
        convB_split<<<dim3(QD / 32, HID / 32), bb>>>(Wq,  Wqbf,  QD, HID);
        convB_split<<<dim3(QD / 32, HID / 32), bb>>>(Wq0, Wq0bf, QD, HID);
        convB_split<<<dim3(QD / 32, HID / 32), bb>>>(Wk,  Wkbf,  QD, HID);
        convB_split<<<dim3(QD / 32, HID / 32), bb>>>(Wv,  Wvbf,  QD, HID);
        convB_split<<<dim3(QD / 32, HID / 32), bb>>>(Wv0, Wv0bf, QD, HID);
        convB_split<<<dim3(HID / 32, MID / 32), bb>>>(W1, W1bf, HID, MID);
        convB_split<<<dim3(MID / 32, HID / 32), bb>>>(W2, W2bf, MID, HID);
    }

    // 3) projections (mma.sync bf16 3-term split)
    gemm_mma<<<dim3(HID / 128, MQ / 128), 256, GEMM_SMEM_BYTES>>>(
        qpbf, Wqbf, bq, qh, nullptr, 3 * QD, HID, 0, 0);
    gemm_mma<<<dim3(HID / 128, MQ / 128), 256, GEMM_SMEM_BYTES>>>(
        qbf, Wq0bf, bq0, q0p, nullptr, 3 * QD, HID, 0, 0);
    gemm_mma<<<dim3(HID / 128, MK / 128), 256, GEMM_SMEM_BYTES>>>(
        kpbf, Wkbf, bk, kh, nullptr, 3 * QD, HID, 0, 0);
    gemm_mma<<<dim3(HID / 128, MK / 128), 256, GEMM_SMEM_BYTES>>>(
        kpbf, Wvbf, bv, v1, nullptr, 3 * QD, HID, 0, 0);
    gemm_mma<<<dim3(HID / 128, MK / 128), 256, GEMM_SMEM_BYTES>>>(
        kpbf, Wv0bf, bv0, v0, nullptr, 3 * QD, HID, 0, 0);

    // 4) scores = qh @ kh^T / 8 (fp32 NT, batched over b,h)
    sgemm_nt<<<dim3(LK / 64, LQ / 64, BB * NH), 256>>>(qh, kh, scores,
        LQ, LK, DH, HID, HID, LK,
        (long long)LQ * HID, (long long)DH,
        (long long)LK * HID, (long long)DH,
        (long long)NH * LQ * LK, (long long)LQ * LK,
        NH, 0.125f);

    // 5) att_out (pre-softmax)
    {
        size_t tot = (size_t)BB * LQ * LK;
        attout_kernel<<<(unsigned)((tot + 255) / 256), 256>>>(scores, out + OFF_ATT);
    }

    // 6) softmax in place
    softmax_kernel<<<BB * NH * LQ, 256>>>(scores);

    // 7) atted_raw = att @ v1 ; tmp = att @ v0
    sgemm_nn<<<dim3(1, LQ / 64, BB * NH), 256>>>(scores, v1, nullptr, atted,
        LQ, DH, LK, LK, HID, HID,
        (long long)NH * LQ * LK, (long long)LQ * LK,
        (long long)LK * HID, (long long)DH,
        (long long)LQ * HID, (long long)DH,
        NH, 1.f, 0);
    sgemm_nn<<<dim3(1, LQ / 64, BB * NH), 256>>>(scores, v0, nullptr, tmp,
        LQ, DH, LK, LK, HID, HID,
        (long long)NH * LQ * LK, (long long)LQ * LK,
        (long long)LK * HID, (long long)DH,
        (long long)LQ * HID, (long long)DH,
        NH, 1.f, 0);

    // 8) bilinear + LN -> x
    bilinear_kernel<<<dim3(HID / 256, BB), 256>>>(q0p, tmp, xraw);
    ln_kernel<<<BB, 256>>>(xraw, nullptr, nx_a, nx_b, out + OFF_X);

    // 9) atted = LN(q0p + atted_raw)
    ln_kernel<<<MQ, 256>>>(q0p, atted, nq_a, nq_b, attln);

    // 10) FFN (mma.sync): h1 kept only as split-bf16 via fused epilogue
    {
        size_t t3 = (size_t)MQ * HID;
        convA_split<<<(unsigned)((t3 + 255) / 256), 256>>>(attln, attlnbf, HID, t3);
    }
    gemm_mma<<<dim3(MID / 128, MQ / 128), 256, GEMM_SMEM_BYTES>>>(
        attlnbf, W1bf, b1, nullptr, h1bf, 3 * HID, 0, MID, 1);
    gemm_mma<<<dim3(HID / 128, MQ / 128), 256, GEMM_SMEM_BYTES>>>(
        h1bf, W2bf, b2, ff, nullptr, 3 * MID, HID, 0, 0);
    ln_kernel<<<MQ, 256>>>(attln, ff, ns_a, ns_b, out + OFF_QQ);
}

// round 6
// speedup vs baseline: 2.6241x; 1.3515x over previous
#include <cuda_runtime.h>
#include <cuda_bf16.h>
#include <math.h>
#include <stdint.h>

// Problem constants
#define BB  8
#define LQ  512
#define LK  1024
#define QD  768
#define HID 1024
#define MID 4096
#define NH  16
#define DH  64

// ---------------- scratch (device globals) ------------------------------------
__device__ float g_qp    [(size_t)BB*LQ*QD];
__device__ float g_q0p   [(size_t)BB*LQ*HID];
__device__ float g_v1    [(size_t)BB*LK*HID];
__device__ float g_v0    [(size_t)BB*LK*HID];
__device__ float g_scores[(size_t)BB*NH*LQ*LK];   // 268 MB fp32 (pre-softmax)
__device__ float g_atted [(size_t)BB*LQ*HID];
__device__ float g_tmp   [(size_t)BB*LQ*HID];
__device__ float g_attln [(size_t)BB*LQ*HID];
__device__ float g_ff    [(size_t)BB*LQ*HID];
__device__ float g_xraw  [(size_t)BB*HID];

// bf16 [hi|lo] split operands (GEMM iterates segments A:[hi,lo,hi] x B:[hi,hi,lo])
__device__ __nv_bfloat16 g_qpbf   [(size_t)BB*LQ*2*QD];
__device__ __nv_bfloat16 g_qbf    [(size_t)BB*LQ*2*QD];
__device__ __nv_bfloat16 g_kpbf   [(size_t)BB*LK*2*QD];
__device__ __nv_bfloat16 g_attlnbf[(size_t)BB*LQ*2*HID];
__device__ __nv_bfloat16 g_h1bf   [(size_t)BB*LQ*2*MID];
__device__ __nv_bfloat16 g_qhs    [(size_t)BB*NH*LQ*2*DH];   // per-head split, x0.125
__device__ __nv_bfloat16 g_khs    [(size_t)BB*NH*LK*2*DH];
__device__ __nv_bfloat16 g_vt     [(size_t)BB*NH*128*2*LK];  // [z][n:v1|v0][hi|lo]
__device__ __nv_bfloat16 g_atts   [(size_t)BB*NH*LQ*2*LK];   // split softmax probs
__device__ __nv_bfloat16 g_Wqbf  [(size_t)HID*2*QD];
__device__ __nv_bfloat16 g_Wq0bf [(size_t)HID*2*QD];
__device__ __nv_bfloat16 g_Wkbf  [(size_t)HID*2*QD];
__device__ __nv_bfloat16 g_Wvbf  [(size_t)HID*2*QD];
__device__ __nv_bfloat16 g_Wv0bf [(size_t)HID*2*QD];
__device__ __nv_bfloat16 g_W1bf  [(size_t)MID*2*HID];
__device__ __nv_bfloat16 g_W2bf  [(size_t)HID*2*MID];

// =================== helpers ==================================================
__device__ __forceinline__ uint32_t smem_u32(const void* p) {
    uint32_t a;
    asm("{ .reg .u64 t; cvta.to.shared.u64 t, %1; cvt.u32.u64 %0, t; }"
        : "=r"(a) : "l"(p));
    return a;
}
#define SWZ128(x) ((x) ^ (((x) >> 3) & 0x70))

__device__ __forceinline__ void cp_async16(uint32_t dst, const void* src) {
    asm volatile("cp.async.cg.shared.global [%0], [%1], 16;"
                 :: "r"(dst), "l"(src) : "memory");
}
#define CP_COMMIT() asm volatile("cp.async.commit_group;" ::: "memory")
#define CP_WAIT(n)  asm volatile("cp.async.wait_group %0;" :: "n"(n) : "memory")

__device__ __forceinline__ void ldsm_x4(uint32_t& r0, uint32_t& r1,
                                        uint32_t& r2, uint32_t& r3, uint32_t a) {
    asm volatile("ldmatrix.sync.aligned.m8n8.x4.shared.b16 {%0,%1,%2,%3}, [%4];"
                 : "=r"(r0), "=r"(r1), "=r"(r2), "=r"(r3) : "r"(a));
}
__device__ __forceinline__ void mma16816(float* c, const uint32_t* a,
                                         uint32_t b0, uint32_t b1) {
    asm volatile("mma.sync.aligned.m16n8k16.row.col.f32.bf16.bf16.f32 "
                 "{%0,%1,%2,%3}, {%4,%5,%6,%7}, {%8,%9}, {%0,%1,%2,%3};"
                 : "+f"(c[0]), "+f"(c[1]), "+f"(c[2]), "+f"(c[3])
                 : "r"(a[0]), "r"(a[1]), "r"(a[2]), "r"(a[3]), "r"(b0), "r"(b1));
}
__device__ __forceinline__ void split2(float v, __nv_bfloat16& hi, __nv_bfloat16& lo) {
    hi = __float2bfloat16(v);
    lo = __float2bfloat16(v - __bfloat162float(hi));
}

// ---------------- split conversions: [hi | lo] --------------------------------
__global__ void convA_split(const float* __restrict__ in, __nv_bfloat16* __restrict__ out,
                            int K, size_t total)
{
    size_t idx = (size_t)blockIdx.x * blockDim.x + threadIdx.x;
    if (idx >= total) return;
    size_t m = idx / K;
    int    k = (int)(idx % K);
    __nv_bfloat16 hi, lo; split2(in[idx], hi, lo);
    __nv_bfloat16* row = out + m * (size_t)(2 * K);
    row[k] = hi; row[K + k] = lo;
}

// W [K,N] fp32 -> [N, 2K] bf16 transposed split
__global__ void convB_split(const float* __restrict__ W, __nv_bfloat16* __restrict__ out,
                            int K, int N)
{
    __shared__ float t[32][33];
    int k0 = blockIdx.x * 32, n0 = blockIdx.y * 32;
    int x = threadIdx.x, y = threadIdx.y;   // 32 x 8
#pragma unroll
    for (int i = 0; i < 32; i += 8)
        t[y + i][x] = W[(size_t)(k0 + y + i) * N + n0 + x];
    __syncthreads();
#pragma unroll
    for (int i = 0; i < 32; i += 8) {
        int n = n0 + y + i, k = k0 + x;
        __nv_bfloat16 hi, lo; split2(t[x][y + i], hi, lo);
        __nv_bfloat16* row = out + (size_t)n * (2 * K);
        row[k] = hi; row[K + k] = lo;
    }
}

// v1,v0 [B*LK, HID] fp32 -> Vt [z=(b,h)][n(0..127: v1 dims | v0 dims)][hi|lo] (2*LK)
__global__ void vt_transpose(const float* __restrict__ v1, const float* __restrict__ v0,
                             __nv_bfloat16* __restrict__ vt)
{
    __shared__ float t[32][33];
    int z = blockIdx.z, b = z >> 4, h = z & 15;
    int kk0 = blockIdx.x * 32, nd0 = blockIdx.y * 32;
    int x = threadIdx.x, y = threadIdx.y;   // 32 x 8
    const float* src = (nd0 < 64) ? v1 : v0;
    int d0 = nd0 & 63;
#pragma unroll
    for (int i = 0; i < 32; i += 8)
        t[y + i][x] = src[(size_t)(b * LK + kk0 + y + i) * HID + h * DH + d0 + x];
    __syncthreads();
#pragma unroll
    for (int i = 0; i < 32; i += 8) {
        int n = nd0 + y + i, kk = kk0 + x;
        __nv_bfloat16 hi, lo; split2(t[x][y + i], hi, lo);
        __nv_bfloat16* row = vt + ((size_t)z * 128 + n) * (2 * LK);
        row[kk] = hi; row[LK + kk] = lo;
    }
}

// ---------------- bf16 mma.sync GEMM ------------------------------------------
// C[M,N] (128x128 CTA tile) = sum over 3 segment-products of A'[.,2K] x B'[.,2K]^T
// segments: A [hi, lo, hi] x B [hi, hi, lo].
// modes: 0 = fp32 C (+z*offC); 1 = split [hi|lo] to Osp (rows 2*Kseg), bias/relu;
//        2 = per-head split to Osp ((b,h) batches, Lrow rows, scale folded);
//        3 = att@V scatter: C=atted, C2=tmp, z=(b,h).
#define GEMM_SMEM_BYTES (2 * (16384 + 16384))

__global__ void __launch_bounds__(256, 2)
gemm_mma(const __nv_bfloat16* __restrict__ A, const __nv_bfloat16* __restrict__ B,
         const float* __restrict__ bias, float* __restrict__ C, float* __restrict__ C2,
         __nv_bfloat16* __restrict__ Osp,
         int K, int ldc,
         long long offA, long long offB, long long offC,
         int mode, int relu, float scale, int Kseg, int Lrow)
{
    extern __shared__ uint8_t dynsmem[];
    const uint32_t sb = smem_u32(dynsmem);
    const int tid = threadIdx.x;
    const int wid = tid >> 5, lane = tid & 31;
    const int m0 = blockIdx.y * 128, n0 = blockIdx.x * 128;
    const int wm = (wid & 3) * 32, wn = (wid >> 2) * 64;
    const int z = blockIdx.z;

    A += (size_t)z * offA;
    B += (size_t)z * offB;

    const int K2 = 2 * K;
    const int cps = K >> 6;          // chunks per segment
    const int nch = 3 * cps;
    const size_t abase = (size_t)m0 * K2;
    const size_t bbase = (size_t)n0 * K2;

    float acc[2][8][4] = {};

    auto load_stage = [&](int st, int ch) {
        int seg = (ch >= cps) ? ((ch >= 2 * cps) ? 2 : 1) : 0;
        int w64 = (ch - seg * cps) * 64;
        int koffA = ((seg == 1) ? K : 0) + w64;
        int koffB = ((seg == 2) ? K : 0) + w64;
        uint32_t base = (uint32_t)st * 32768u;
#pragma unroll
        for (int i = 0; i < 4; i++) {
            int idx = tid + i * 256;
            int r = idx >> 3, c = idx & 7;
            uint32_t so = SWZ128((uint32_t)(r * 128 + c * 16));
            cp_async16(sb + base + so, A + abase + (size_t)r * K2 + koffA + c * 8);
            cp_async16(sb + base + 16384u + so, B + bbase + (size_t)r * K2 + koffB + c * 8);
        }
        CP_COMMIT();
    };

    load_stage(0, 0);

    for (int ch = 0; ch < nch; ch++) {
        if (ch + 1 < nch) { load_stage((ch + 1) & 1, ch + 1); CP_WAIT(1); }
        else              { CP_WAIT(0); }
        __syncthreads();

        uint32_t As = sb + (uint32_t)(ch & 1) * 32768u;
        uint32_t Bs = As + 16384u;
#pragma unroll
        for (int ks = 0; ks < 4; ks++) {
            int kb = ks * 32 + ((lane >> 4) << 4);
            uint32_t a[2][4];
#pragma unroll
            for (int mi = 0; mi < 2; mi++) {
                int r = wm + mi * 16 + (lane & 15);
                ldsm_x4(a[mi][0], a[mi][1], a[mi][2], a[mi][3],
                        As + SWZ128((uint32_t)(r * 128 + kb)));
            }
            uint32_t b[4][4];
#pragma unroll
            for (int g = 0; g < 4; g++) {
                int r = wn + g * 16 + (lane & 15);
                ldsm_x4(b[g][0], b[g][1], b[g][2], b[g][3],
                        Bs + SWZ128((uint32_t)(r * 128 + kb)));
            }
#pragma unroll
            for (int mi = 0; mi < 2; mi++)
#pragma unroll
                for (int nj = 0; nj < 8; nj++) {
                    int g = nj >> 1;
                    uint32_t b0 = (nj & 1) ? b[g][1] : b[g][0];
                    uint32_t b1 = (nj & 1) ? b[g][3] : b[g][2];
                    mma16816(acc[mi][nj], a[mi], b0, b1);
                }
        }
        __syncthreads();
    }

    // ---- epilogue ----
    int rowg = lane >> 2, colg = (lane & 3) * 2;
#pragma unroll
    for (int mi = 0; mi < 2; mi++) {
#pragma unroll
        for (int nj = 0; nj < 8; nj++) {
            int c0 = n0 + wn + nj * 8 + colg;
            float bx = 0.f, by = 0.f;
            if (bias) { bx = bias[c0]; by = bias[c0 + 1]; }
#pragma unroll
            for (int half = 0; half < 2; half++) {
                int r = m0 + wm + mi * 16 + rowg + half * 8;
                float vx = (acc[mi][nj][half * 2 + 0] + bx) * scale;
                float vy = (acc[mi][nj][half * 2 + 1] + by) * scale;
                if (relu) { vx = fmaxf(vx, 0.f); vy = fmaxf(vy, 0.f); }
                if (mode == 0) {
                    float2 p = {vx, vy};
                    *(float2*)(C + (size_t)z * offC + (size_t)r * ldc + c0) = p;
                } else if (mode == 1) {
                    __nv_bfloat162 hp, lp;
                    split2(vx, hp.x, lp.x); split2(vy, hp.y, lp.y);
                    __nv_bfloat16* rw = Osp + (size_t)r * (2 * Kseg) + c0;
                    *(__nv_bfloat162*)(rw)        = hp;
                    *(__nv_bfloat162*)(rw + Kseg) = lp;
                } else if (mode == 2) {
                    int zz = (r / Lrow) * NH + (c0 >> 6);
                    int rr = r % Lrow, cc = c0 & 63;
                    __nv_bfloat162 hp, lp;
                    split2(vx, hp.x, lp.x); split2(vy, hp.y, lp.y);
                    __nv_bfloat16* rw = Osp + ((size_t)zz * Lrow + rr) * (2 * DH) + cc;
                    *(__nv_bfloat162*)(rw)      = hp;
                    *(__nv_bfloat162*)(rw + DH) = lp;
                } else { // mode 3
                    int b = z >> 4, h = z & 15;
                    float* dst = (c0 < 64) ? C : C2;
                    float2 p = {vx, vy};
                    *(float2*)(dst + ((size_t)(b * LQ + r)) * HID + h * DH + (c0 & 63)) = p;
                }
            }
        }
    }
}

// ---------------- positional encoding add ------------------------------------
__global__ void add_pe_kernel(const float* __restrict__ in, float* __restrict__ out,
                              int L, size_t total)
{
    size_t idx = (size_t)blockIdx.x * blockDim.x + threadIdx.x;
    if (idx >= total) return;
    int c = (int)(idx % QD);
    int l = (int)((idx / QD) % L);
    const float coef = -9.210340371976184f / 768.0f;   // -ln(10000)/dim
    float ang = (float)l * expf((float)(c & ~1) * coef);
    float pe  = (c & 1) ? cosf(ang) : sinf(ang);
    out[idx] = in[idx] + pe;
}

// ---------------- fused softmax + att_out -------------------------------------
// block = one (b, q): 16 warps, warp w = head w. Raw scores staged in shared
// for att_out; softmax written as split bf16 [hi(1024)|lo(1024)] rows.
__global__ void __launch_bounds__(512)
softmax_attout(const float* __restrict__ scores, __nv_bfloat16* __restrict__ atts,
               float* __restrict__ attout)
{
    extern __shared__ float sh[];   // 16 * 1024 floats
    int bx = blockIdx.x;
    int b = bx >> 9, q = bx & 511;
    int tid = threadIdx.x, w = tid >> 5, lane = tid & 31;

    const float* row = scores + ((size_t)(b * NH + w) * LQ + q) * LK;
    float4 v4[8];
    float mx = -INFINITY;
#pragma unroll
    for (int j = 0; j < 8; j++) {
        int i4 = lane + j * 32;
        v4[j] = *(const float4*)(row + i4 * 4);
        *(float4*)(sh + w * 1024 + i4 * 4) = v4[j];
        mx = fmaxf(mx, fmaxf(fmaxf(v4[j].x, v4[j].y), fmaxf(v4[j].z, v4[j].w)));
    }
#pragma unroll
    for (int o = 16; o > 0; o >>= 1) mx = fmaxf(mx, __shfl_xor_sync(0xFFFFFFFFu, mx, o));
    float sum = 0.f;
#pragma unroll
    for (int j = 0; j < 8; j++) {
        v4[j].x = expf(v4[j].x - mx); v4[j].y = expf(v4[j].y - mx);
        v4[j].z = expf(v4[j].z - mx); v4[j].w = expf(v4[j].w - mx);
        sum += (v4[j].x + v4[j].y) + (v4[j].z + v4[j].w);
    }
#pragma unroll
    for (int o = 16; o > 0; o >>= 1) sum += __shfl_xor_sync(0xFFFFFFFFu, sum, o);
    float inv = 1.f / sum;

    __nv_bfloat16* arow = atts + ((size_t)(b * NH + w) * LQ + q) * (2 * LK);
#pragma unroll
    for (int j = 0; j < 8; j++) {
        int c = (lane + j * 32) * 4;
        float p0 = v4[j].x * inv, p1 = v4[j].y * inv;
        float p2 = v4[j].z * inv, p3 = v4[j].w * inv;
        __nv_bfloat162 h01, l01, h23, l23;
        split2(p0, h01.x, l01.x); split2(p1, h01.y, l01.y);
        split2(p2, h23.x, l23.x); split2(p3, h23.y, l23.y);
        *(__nv_bfloat162*)(arow + c)            = h01;
        *(__nv_bfloat162*)(arow + c + 2)        = h23;
        *(__nv_bfloat162*)(arow + LK + c)       = l01;
        *(__nv_bfloat162*)(arow + LK + c + 2)   = l23;
    }
    __syncthreads();

    // att_out: relu over raw scores, mean over heads
    float s1 = 0.f, s2 = 0.f;
#pragma unroll
    for (int h = 0; h < NH; h++) {
        s1 += fmaxf(sh[h * 1024 + tid], 0.f);
        s2 += fmaxf(sh[h * 1024 + tid + 512], 0.f);
    }
    float* orow = attout + ((size_t)b * LQ + q) * LK;
    orow[tid]       = s1 * (1.f / NH);
    orow[tid + 512] = s2 * (1.f / NH);
}

// ---------------- bilinear reduce --------------------------------------------
__global__ void bilinear_kernel(const float* __restrict__ q0p,
                                const float* __restrict__ tmp,
                                float* __restrict__ xraw)
{
    int c = blockIdx.x * blockDim.x + threadIdx.x;
    int b = blockIdx.y;
    const float* a = q0p + (size_t)b * LQ * HID + c;
    const float* t = tmp + (size_t)b * LQ * HID + c;
    float s = 0.f;
    for (int v = 0; v < LQ; v++)
        s += a[(size_t)v * HID] * t[(size_t)v * HID];
    xraw[b * HID + c] = s;
}

// ---------------- custom LayerNorm -------------------------------------------
__global__ void __launch_bounds__(256)
ln_kernel(const float* __restrict__ in1, const float* __restrict__ in2,
          const float* __restrict__ ga, const float* __restrict__ gb,
          float* __restrict__ out)
{
    size_t row = blockIdx.x;
    int t = threadIdx.x;
    const float* p1 = in1 + row * (size_t)HID;
    const float* p2 = in2 ? in2 + row * (size_t)HID : nullptr;
    float v[4];
    float s = 0.f;
#pragma unroll
    for (int i = 0; i < 4; i++) {
        int c = t + i * 256;
        v[i] = p1[c] + (p2 ? p2[c] : 0.f);
        s += v[i];
    }
    __shared__ float red[256];
    red[t] = s; __syncthreads();
    for (int o = 128; o > 0; o >>= 1) { if (t < o) red[t] += red[t + o]; __syncthreads(); }
    float mean = red[0] * (1.f / (float)HID);
    __syncthreads();
    float s2 = 0.f;
#pragma unroll
    for (int i = 0; i < 4; i++) { float d = v[i] - mean; s2 += d * d; }
    red[t] = s2; __syncthreads();
    for (int o = 128; o > 0; o >>= 1) { if (t < o) red[t] += red[t + o]; __syncthreads(); }
    float var = red[0] * (1.f / (float)(HID - 1));
    float inv = 1.f / (sqrtf(var) + 1e-6f);
#pragma unroll
    for (int i = 0; i < 4; i++) {
        int c = t + i * 256;
        out[row * (size_t)HID + c] = ga[c] * (v[i] - mean) * inv + gb[c];
    }
}

// =============================================================================
extern "C" void kernel_launch(void* const* d_in, const int* in_sizes, int n_in,
                              void* d_out, int out_size)
{
    const float* q    = (const float*)d_in[0];
    const float* k    = (const float*)d_in[1];
    const float* Wq   = (const float*)d_in[2];
    const float* bq   = (const float*)d_in[3];
    const float* Wk   = (const float*)d_in[4];
    const float* bk   = (const float*)d_in[5];
    const float* Wv   = (const float*)d_in[6];
    const float* bv   = (const float*)d_in[7];
    const float* Wv0  = (const float*)d_in[8];
    const float* bv0  = (const float*)d_in[9];
    const float* Wq0  = (const float*)d_in[10];
    const float* bq0  = (const float*)d_in[11];
    const float* nq_a = (const float*)d_in[12];
    const float* nq_b = (const float*)d_in[13];
    const float* nx_a = (const float*)d_in[14];
    const float* nx_b = (const float*)d_in[15];
    const float* W1   = (const float*)d_in[16];
    const float* b1   = (const float*)d_in[17];
    const float* W2   = (const float*)d_in[18];
    const float* b2   = (const float*)d_in[19];
    const float* ns_a = (const float*)d_in[20];
    const float* ns_b = (const float*)d_in[21];

    float* out = (float*)d_out;
    const size_t OFF_X   = 0;
    const size_t OFF_QQ  = OFF_X  + (size_t)BB * HID;
    const size_t OFF_KP  = OFF_QQ + (size_t)BB * LQ * HID;
    const size_t OFF_ATT = OFF_KP + (size_t)BB * LK * QD;

    float *qp, *q0p, *v1, *v0, *scores, *atted, *tmp, *attln, *ff, *xraw;
    __nv_bfloat16 *qpbf, *qbf, *kpbf, *attlnbf, *h1bf, *qhs, *khs, *vt, *atts;
    __nv_bfloat16 *Wqbf, *Wq0bf, *Wkbf, *Wvbf, *Wv0bf, *W1bf, *W2bf;
    cudaGetSymbolAddress((void**)&qp,     g_qp);
    cudaGetSymbolAddress((void**)&q0p,    g_q0p);
    cudaGetSymbolAddress((void**)&v1,     g_v1);
    cudaGetSymbolAddress((void**)&v0,     g_v0);
    cudaGetSymbolAddress((void**)&scores, g_scores);
    cudaGetSymbolAddress((void**)&atted,  g_atted);
    cudaGetSymbolAddress((void**)&tmp,    g_tmp);
    cudaGetSymbolAddress((void**)&attln,  g_attln);
    cudaGetSymbolAddress((void**)&ff,     g_ff);
    cudaGetSymbolAddress((void**)&xraw,   g_xraw);
    cudaGetSymbolAddress((void**)&qpbf,   g_qpbf);
    cudaGetSymbolAddress((void**)&qbf,    g_qbf);
    cudaGetSymbolAddress((void**)&kpbf,   g_kpbf);
    cudaGetSymbolAddress((void**)&attlnbf,g_attlnbf);
    cudaGetSymbolAddress((void**)&h1bf,   g_h1bf);
    cudaGetSymbolAddress((void**)&qhs,    g_qhs);
    cudaGetSymbolAddress((void**)&khs,    g_khs);
    cudaGetSymbolAddress((void**)&vt,     g_vt);
    cudaGetSymbolAddress((void**)&atts,   g_atts);
    cudaGetSymbolAddress((void**)&Wqbf,   g_Wqbf);
    cudaGetSymbolAddress((void**)&Wq0bf,  g_Wq0bf);
    cudaGetSymbolAddress((void**)&Wkbf,   g_Wkbf);
    cudaGetSymbolAddress((void**)&Wvbf,   g_Wvbf);
    cudaGetSymbolAddress((void**)&Wv0bf,  g_Wv0bf);
    cudaGetSymbolAddress((void**)&W1bf,   g_W1bf);
    cudaGetSymbolAddress((void**)&W2bf,   g_W2bf);

    cudaFuncSetAttribute(gemm_mma, cudaFuncAttributeMaxDynamicSharedMemorySize,
                         GEMM_SMEM_BYTES);
    cudaFuncSetAttribute(softmax_attout, cudaFuncAttributeMaxDynamicSharedMemorySize,
                         16 * 1024 * (int)sizeof(float));

    float* kp = out + OFF_KP;
    const int MQ = BB * LQ;     // 4096
    const int MK = BB * LK;     // 8192

    // 1) positional encodings
    {
        size_t tq = (size_t)BB * LQ * QD;
        add_pe_kernel<<<(unsigned)((tq + 255) / 256), 256>>>(q, qp, LQ, tq);
        size_t tk = (size_t)BB * LK * QD;
        add_pe_kernel<<<(unsigned)((tk + 255) / 256), 256>>>(k, kp, LK, tk);
    }

    // 2) split conversions
    {
        size_t t1 = (size_t)MQ * QD;
        convA_split<<<(unsigned)((t1 + 255) / 256), 256>>>(qp, qpbf, QD, t1);
        convA_split<<<(unsigned)((t1 + 255) / 256), 256>>>(q,  qbf,  QD, t1);
        size_t t2 = (size_t)MK * QD;
        convA_split<<<(unsigned)((t2 + 255) / 256), 256>>>(kp, kpbf, QD, t2);
        dim3 bb(32, 8);
        convB_split<<<dim3(QD / 32, HID / 32), bb>>>(Wq,  Wqbf,  QD, HID);
        convB_split<<<dim3(QD / 32, HID / 32), bb>>>(Wq0, Wq0bf, QD, HID);
        convB_split<<<dim3(QD / 32, HID / 32), bb>>>(Wk,  Wkbf,  QD, HID);
        convB_split<<<dim3(QD / 32, HID / 32), bb>>>(Wv,  Wvbf,  QD, HID);
        convB_split<<<dim3(QD / 32, HID / 32), bb>>>(Wv0, Wv0bf, QD, HID);
        convB_split<<<dim3(HID / 32, MID / 32), bb>>>(W1, W1bf, HID, MID);
        convB_split<<<dim3(MID / 32, HID / 32), bb>>>(W2, W2bf, MID, HID);
    }

    // 3) projections
    //    qh -> per-head split with 1/8 folded (mode 2)
    gemm_mma<<<dim3(HID / 128, MQ / 128, 1), 256, GEMM_SMEM_BYTES>>>(
        qpbf, Wqbf, bq, nullptr, nullptr, qhs,
        QD, 0, 0, 0, 0, 2, 0, 0.125f, 0, LQ);
    //    kh -> per-head split (mode 2)
    gemm_mma<<<dim3(HID / 128, MK / 128, 1), 256, GEMM_SMEM_BYTES>>>(
        kpbf, Wkbf, bk, nullptr, nullptr, khs,
        QD, 0, 0, 0, 0, 2, 0, 1.f, 0, LK);
    //    q0p fp32 (mode 0)
    gemm_mma<<<dim3(HID / 128, MQ / 128, 1), 256, GEMM_SMEM_BYTES>>>(
        qbf, Wq0bf, bq0, q0p, nullptr, nullptr,
        QD, HID, 0, 0, 0, 0, 0, 1.f, 0, 0);
    //    v1, v0 fp32 (mode 0)
    gemm_mma<<<dim3(HID / 128, MK / 128, 1), 256, GEMM_SMEM_BYTES>>>(
        kpbf, Wvbf, bv, v1, nullptr, nullptr,
        QD, HID, 0, 0, 0, 0, 0, 1.f, 0, 0);
    gemm_mma<<<dim3(HID / 128, MK / 128, 1), 256, GEMM_SMEM_BYTES>>>(
        kpbf, Wv0bf, bv0, v0, nullptr, nullptr,
        QD, HID, 0, 0, 0, 0, 0, 1.f, 0, 0);

    // 4) Vt transpose-split
    vt_transpose<<<dim3(LK / 32, 128 / 32, BB * NH), dim3(32, 8)>>>(v1, v0, vt);

    // 5) scores = qhs @ khs^T (batched HMMA, K=64, pre-scaled)
    gemm_mma<<<dim3(LK / 128, LQ / 128, BB * NH), 256, GEMM_SMEM_BYTES>>>(
        qhs, khs, nullptr, scores, nullptr, nullptr,
        DH, LK,
        (long long)LQ * 2 * DH, (long long)LK * 2 * DH, (long long)LQ * LK,
        0, 0, 1.f, 0, 0);

    // 6) fused softmax (split bf16 out) + att_out
    softmax_attout<<<BB * LQ, 512, 16 * 1024 * sizeof(float)>>>(
        scores, atts, out + OFF_ATT);

    // 7) [atted | tmp] = att @ [v1 | v0] (batched HMMA, N=128, K=1024)
    gemm_mma<<<dim3(1, LQ / 128, BB * NH), 256, GEMM_SMEM_BYTES>>>(
        atts, vt, nullptr, atted, tmp, nullptr,
        LK, 0,
        (long long)LQ * 2 * LK, (long long)128 * 2 * LK, 0,
        3, 0, 1.f, 0, 0);

    // 8) bilinear + LN -> x
    bilinear_kernel<<<dim3(HID / 256, BB), 256>>>(q0p, tmp, xraw);
    ln_kernel<<<BB, 256>>>(xraw, nullptr, nx_a, nx_b, out + OFF_X);

    // 9) atted = LN(q0p + atted_raw)
    ln_kernel<<<MQ, 256>>>(q0p, atted, nq_a, nq_b, attln);

    // 10) FFN: FFN1 emits split h1 directly; FFN2 -> ff; final LN -> qq
    {
        size_t t3 = (size_t)MQ * HID;
        convA_split<<<(unsigned)((t3 + 255) / 256), 256>>>(attln, attlnbf, HID, t3);
    }
    gemm_mma<<<dim3(MID / 128, MQ / 128, 1), 256, GEMM_SMEM_BYTES>>>(
        attlnbf, W1bf, b1, nullptr, nullptr, h1bf,
        HID, 0, 0, 0, 0, 1, 1, 1.f, MID, 0);
    gemm_mma<<<dim3(HID / 128, MQ / 128, 1), 256, GEMM_SMEM_BYTES>>>(
        h1bf, W2bf, b2, ff, nullptr, nullptr,
        MID, HID, 0, 0, 0, 0, 0, 1.f, 0, 0);
    ln_kernel<<<MQ, 256>>>(attln, ff, ns_a, ns_b, out + OFF_QQ);
}